// round 15
// baseline (speedup 1.0000x reference)
#include <cuda_runtime.h>
#include <cuda_bf16.h>

// Circular self-convolution via half-length real FFT (radix-4), THREE rows
// per CTA interleaved in-thread. 128 CTAs x 128 threads (384 rows total):
//  - 128 CTAs <= 148 SMs: exactly one CTA per SM, no double-loaded tail
//  - each thread runs its butterfly for 3 independent rows -> 3 dependency
//    chains per thread (hides LDS latency at 1 warp/SMSP)
//  - per-stage twiddles computed ONCE via MUFU sin/cos.approx (all angles
//    <= pi/2, accurate regime; fwd/inv recompute identical values so the
//    unwind is exact) and shared by all 3 rows; no twiddle table
// Skeleton identical to R13: u[m]=x[2m]+i*x[2m+1] -> FFT-512 (radix-4 DIF,
// L=512,128,32,8 + radix-2) -> rfft combine + square + inverse-pack
// (pairwise in-place, exclusive ownership) -> exact inverse -> de-pack.

#define N_CONV 1024
#define HF 512
#define THREADS 128

#define P2(i) ((i) + ((i) >> 4))

// Position of frequency k after stages r4(512),r4(128),r4(32),r4(8),r2(2).
__device__ __forceinline__ int rev_inv(int k) {
    return ((k & 3) << 7) | (((k >> 2) & 3) << 5) | (((k >> 4) & 3) << 3)
         | (((k >> 6) & 3) << 1) | ((k >> 8) & 1);
}

__device__ __forceinline__ float fsin(float x) {
    float r; asm("sin.approx.f32 %0, %1;" : "=f"(r) : "f"(x)); return r;
}
__device__ __forceinline__ float fcos(float x) {
    float r; asm("cos.approx.f32 %0, %1;" : "=f"(r) : "f"(x)); return r;
}

__device__ __forceinline__ float2 cadd(float2 a, float2 b) { return make_float2(a.x + b.x, a.y + b.y); }
__device__ __forceinline__ float2 csub(float2 a, float2 b) { return make_float2(a.x - b.x, a.y - b.y); }
__device__ __forceinline__ float2 cmul(float2 a, float2 w) {
    return make_float2(a.x * w.x - a.y * w.y, a.x * w.y + a.y * w.x);
}
__device__ __forceinline__ float2 cmulc(float2 a, float2 w) {   // a * conj(w)
    return make_float2(a.x * w.x + a.y * w.y, a.y * w.x - a.x * w.y);
}
__device__ __forceinline__ float2 submuli(float2 a, float2 b) {  // a - i*b
    return make_float2(a.x + b.y, a.y - b.x);
}
__device__ __forceinline__ float2 addmuli(float2 a, float2 b) {  // a + i*b
    return make_float2(a.x - b.y, a.y + b.x);
}
__device__ __forceinline__ float2 csq(float2 a) {
    return make_float2(a.x * a.x - a.y * a.y, 2.0f * a.x * a.y);
}

// w1 = e^{-i th}, w2 = w1^2, w3 = w1^3.
__device__ __forceinline__ void tw3(float th, float2& w1, float2& w2, float2& w3)
{
    w1 = make_float2(fcos(th), -fsin(th));
    w2 = cmul(w1, w1);
    w3 = cmul(w1, w2);
}

// Forward DIF radix-4 stage for all 3 rows (twiddles shared).
template<int L>
__device__ __forceinline__ void fwd_stage(float2* X0, float2* X1, float2* X2,
                                          int t)
{
    const int q    = L >> 2;
    const int blk  = t / q;
    const int pos  = t % q;
    const int base = blk * L + pos;
    const int i0 = P2(base), i1 = P2(base + q), i2 = P2(base + 2*q), i3 = P2(base + 3*q);

    float2 w1, w2, w3;
    tw3((float)pos * (6.283185307179586f / (float)L), w1, w2, w3);

    float2* Xs[3] = {X0, X1, X2};
    #pragma unroll
    for (int s = 0; s < 3; ++s) {
        float2* X = Xs[s];
        const float2 a0 = X[i0], a1 = X[i1], a2 = X[i2], a3 = X[i3];
        const float2 t0 = cadd(a0, a2);
        const float2 t1 = csub(a0, a2);
        const float2 t2 = cadd(a1, a3);
        const float2 t3 = csub(a1, a3);
        X[i0] = cadd(t0, t2);
        X[i1] = cmul(submuli(t1, t3), w1);
        X[i2] = cmul(csub(t0, t2), w2);
        X[i3] = cmul(addmuli(t1, t3), w3);
    }
}

// Inverse radix-4 stage (un-twiddle by conj, inverse butterfly), 3 rows.
template<int L>
__device__ __forceinline__ void inv_stage(float2* X0, float2* X1, float2* X2,
                                          int t)
{
    const int q    = L >> 2;
    const int blk  = t / q;
    const int pos  = t % q;
    const int base = blk * L + pos;
    const int i0 = P2(base), i1 = P2(base + q), i2 = P2(base + 2*q), i3 = P2(base + 3*q);

    float2 w1, w2, w3;
    tw3((float)pos * (6.283185307179586f / (float)L), w1, w2, w3);

    float2* Xs[3] = {X0, X1, X2};
    #pragma unroll
    for (int s = 0; s < 3; ++s) {
        float2* X = Xs[s];
        const float2 a0 = X[i0];
        const float2 a1 = cmulc(X[i1], w1);
        const float2 a2 = cmulc(X[i2], w2);
        const float2 a3 = cmulc(X[i3], w3);
        const float2 t0 = cadd(a0, a2);
        const float2 t1 = csub(a0, a2);
        const float2 t2 = cadd(a1, a3);
        const float2 t3 = csub(a1, a3);
        X[i0] = cadd(t0, t2);
        X[i1] = addmuli(t1, t3);
        X[i2] = csub(t0, t2);
        X[i3] = submuli(t1, t3);
    }
}

// Radix-2 stage L=2 (thread-local pairs; same butterfly fwd and inv).
__device__ __forceinline__ void r2_stage(float2* X0, float2* X1, float2* X2,
                                         int t)
{
    const int b = 4 * t;
    const int i0 = P2(b), i1 = P2(b + 1), i2 = P2(b + 2), i3 = P2(b + 3);
    float2* Xs[3] = {X0, X1, X2};
    #pragma unroll
    for (int s = 0; s < 3; ++s) {
        float2* X = Xs[s];
        const float2 a0 = X[i0], a1 = X[i1], a2 = X[i2], a3 = X[i3];
        X[i0] = cadd(a0, a1);
        X[i1] = csub(a0, a1);
        X[i2] = cadd(a2, a3);
        X[i3] = csub(a2, a3);
    }
}

// Middle unit for pair (k, 512-k), all 3 rows (w shared): rfft combine +
// square + inverse-pack. Reads/writes only its own two positions.
__device__ __forceinline__ void middle_unit(float2* X0, float2* X1, float2* X2,
                                            int k)
{
    const int pk = P2(rev_inv(k));
    const int pm = P2(rev_inv((HF - k) & (HF - 1)));

    const float th = (float)k * 0.006135923151542565f;    // pi/512
    const float2 w = make_float2(fcos(th), -fsin(th));    // W1024^k

    float2* Xs[3] = {X0, X1, X2};
    #pragma unroll
    for (int s = 0; s < 3; ++s) {
        float2* X = Xs[s];
        const float2 Uk = X[pk];
        const float2 Um = X[pm];

        const float2 E = make_float2(0.5f * (Uk.x + Um.x), 0.5f * (Uk.y - Um.y));
        const float2 O = make_float2(0.5f * (Uk.y + Um.y), 0.5f * (Um.x - Uk.x));

        const float2 wO = cmul(O, w);
        const float2 Xp = cadd(E, wO);             // X[k]
        const float2 Xm = csub(E, wO);             // X[k+512]

        const float2 P = csq(Xp);
        const float2 M = csq(Xm);
        const float2 S  = make_float2(0.5f * (P.x + M.x), 0.5f * (P.y + M.y));
        const float2 Dm = make_float2(0.5f * (P.x - M.x), 0.5f * (P.y - M.y));

        const float2 r = cmulc(Dm, w);             // conj(w)*Dm
        const float2 Vk = make_float2(S.x - r.y, S.y + r.x);     // S + i*r

        const float2 q2 = cmul(make_float2(Dm.x, -Dm.y), w);     // w*conj(Dm)
        const float2 Vm = make_float2(S.x - q2.y, -S.y + q2.x);  // conj(S)+i*q2

        X[pk] = Vk;
        X[pm] = Vm;
    }
}

__global__ __launch_bounds__(THREADS, 1)
void mcf_r4x3_kernel(const float* __restrict__ x1,
                     const float* __restrict__ x2,
                     const float* __restrict__ x3,
                     float* __restrict__ out)
{
    __shared__ __align__(16) float2 XA[546];
    __shared__ __align__(16) float2 XB[546];
    __shared__ __align__(16) float2 XC[546];

    const int bx = blockIdx.x;                 // 0..127: rows 3bx..3bx+2
    const int t  = threadIdx.x;                // 0..127

    const float* xr[3];
    float* orow[3];
    #pragma unroll
    for (int s = 0; s < 3; ++s) {
        const int r   = 3 * bx + s;
        const int arr = r >> 7;
        const int row = r & 127;
        const float* xp = (arr == 0) ? x1 : ((arr == 1) ? x2 : x3);
        xr[s]   = xp + (size_t)row * N_CONV;
        orow[s] = out + (size_t)arr * 128 * N_CONV + (size_t)row * N_CONV;
    }

    // Prologue: pack u[m] = x[2m] + i*x[2m+1]; thread t owns m = 4t..4t+3.
    {
        float2* Xs[3] = {XA, XB, XC};
        #pragma unroll
        for (int s = 0; s < 3; ++s) {
            const float4 v0 = ((const float4*)xr[s])[2 * t];
            const float4 v1 = ((const float4*)xr[s])[2 * t + 1];
            const int b = 4 * t;
            Xs[s][P2(b)]     = make_float2(v0.x, v0.y);
            Xs[s][P2(b + 1)] = make_float2(v0.z, v0.w);
            Xs[s][P2(b + 2)] = make_float2(v1.x, v1.y);
            Xs[s][P2(b + 3)] = make_float2(v1.z, v1.w);
        }
    }
    __syncthreads();

    // Forward FFT-512.
    fwd_stage<512>(XA, XB, XC, t); __syncthreads();
    fwd_stage<128>(XA, XB, XC, t); __syncwarp();
    fwd_stage< 32>(XA, XB, XC, t); __syncwarp();
    fwd_stage<  8>(XA, XB, XC, t); __syncwarp();
    r2_stage(XA, XB, XC, t);
    __syncthreads();   // middle reads scattered global positions

    // Middle: rfft combine + square + inverse-pack, pairwise in-place.
    middle_unit(XA, XB, XC, 2 * t);
    middle_unit(XA, XB, XC, 2 * t + 1);
    if (t == 0) middle_unit(XA, XB, XC, 256);
    __syncthreads();

    // Inverse: exact unwind.
    r2_stage(XA, XB, XC, t);       __syncwarp();
    inv_stage<  8>(XA, XB, XC, t); __syncwarp();
    inv_stage< 32>(XA, XB, XC, t); __syncwarp();
    inv_stage<128>(XA, XB, XC, t); __syncthreads();

    // Final inverse stage L=512 fused with epilogue de-pack to gmem.
    {
        const int i0 = P2(t), i1 = P2(t + 128), i2 = P2(t + 256), i3 = P2(t + 384);
        float2 w1, w2, w3;
        tw3((float)t * (6.283185307179586f / 512.0f), w1, w2, w3);
        const float inv_n = 1.0f / 512.0f;

        float2* Xs[3] = {XA, XB, XC};
        #pragma unroll
        for (int s = 0; s < 3; ++s) {
            float2* X = Xs[s];
            const float2 a0 = X[i0];
            const float2 a1 = cmulc(X[i1], w1);
            const float2 a2 = cmulc(X[i2], w2);
            const float2 a3 = cmulc(X[i3], w3);

            const float2 t0 = cadd(a0, a2);
            const float2 t1 = csub(a0, a2);
            const float2 t2 = cadd(a1, a3);
            const float2 t3 = csub(a1, a3);

            const float2 v0 = cadd(t0, t2);        // v[t]
            const float2 v1 = addmuli(t1, t3);     // v[t+128]
            const float2 v2 = csub(t0, t2);        // v[t+256]
            const float2 v3 = submuli(t1, t3);     // v[t+384]

            float2* o2 = (float2*)orow[s];
            o2[t]       = make_float2(v0.x * inv_n, v0.y * inv_n);
            o2[t + 128] = make_float2(v1.x * inv_n, v1.y * inv_n);
            o2[t + 256] = make_float2(v2.x * inv_n, v2.y * inv_n);
            o2[t + 384] = make_float2(v3.x * inv_n, v3.y * inv_n);
        }
    }
}

extern "C" void kernel_launch(void* const* d_in, const int* in_sizes, int n_in,
                              void* d_out, int out_size)
{
    const float* x1 = (const float*)d_in[0];
    const float* x2 = (const float*)d_in[1];
    const float* x3 = (const float*)d_in[2];
    float* out = (float*)d_out;

    mcf_r4x3_kernel<<<128, THREADS>>>(x1, x2, x3, out);
}

// round 16
// speedup vs baseline: 1.1525x; 1.1525x over previous
#include <cuda_runtime.h>
#include <cuda_bf16.h>

// Circular self-convolution via half-length real FFT (radix-4), one row per
// CTA. 384 CTAs x 128 threads (R13 skeleton — best measured configuration:
// 3 CTAs/SM = 12 warps/SM as independent barrier domains).
//
// R16 = R13 + validated instruction cuts, no structural change:
//  - MUFU twiddles per stage (sin/cos.approx, angles < pi/2), NO table:
//    kills sincospif prologue + table STS + per-stage table LDS. fwd/inv
//    recompute identical values so the unwind stays exact.
//  - 1/512 normalization folded into the middle's 1/2 factors (epilogue
//    stores raw).
// Flow: u[m]=x[2m]+i*x[2m+1] -> FFT-512 (radix-4 DIF L=512,128,32,8 + r2)
// -> rfft combine + square + inverse-pack (pairwise in-place, exclusive
// ownership) -> exact stage-by-stage inverse -> de-pack to gmem.

#define N_CONV 1024
#define HF 512
#define THREADS 128

#define P2(i) ((i) + ((i) >> 4))

// Position of frequency k after stages r4(512),r4(128),r4(32),r4(8),r2(2).
__device__ __forceinline__ int rev_inv(int k) {
    return ((k & 3) << 7) | (((k >> 2) & 3) << 5) | (((k >> 4) & 3) << 3)
         | (((k >> 6) & 3) << 1) | ((k >> 8) & 1);
}

__device__ __forceinline__ float fsin(float x) {
    float r; asm("sin.approx.f32 %0, %1;" : "=f"(r) : "f"(x)); return r;
}
__device__ __forceinline__ float fcos(float x) {
    float r; asm("cos.approx.f32 %0, %1;" : "=f"(r) : "f"(x)); return r;
}

__device__ __forceinline__ float2 cadd(float2 a, float2 b) { return make_float2(a.x + b.x, a.y + b.y); }
__device__ __forceinline__ float2 csub(float2 a, float2 b) { return make_float2(a.x - b.x, a.y - b.y); }
__device__ __forceinline__ float2 cmul(float2 a, float2 w) {
    return make_float2(a.x * w.x - a.y * w.y, a.x * w.y + a.y * w.x);
}
__device__ __forceinline__ float2 cmulc(float2 a, float2 w) {   // a * conj(w)
    return make_float2(a.x * w.x + a.y * w.y, a.y * w.x - a.x * w.y);
}
__device__ __forceinline__ float2 submuli(float2 a, float2 b) {  // a - i*b
    return make_float2(a.x + b.y, a.y - b.x);
}
__device__ __forceinline__ float2 addmuli(float2 a, float2 b) {  // a + i*b
    return make_float2(a.x - b.y, a.y + b.x);
}
__device__ __forceinline__ float2 csq(float2 a) {
    return make_float2(a.x * a.x - a.y * a.y, 2.0f * a.x * a.y);
}

// w1 = e^{-i th}, w2 = w1^2, w3 = w1^3.  (th < pi/2 at every call site)
__device__ __forceinline__ void tw3(float th, float2& w1, float2& w2, float2& w3)
{
    w1 = make_float2(fcos(th), -fsin(th));
    w2 = cmul(w1, w1);
    w3 = cmul(w1, w2);
}

// Forward DIF radix-4 stage, in-place, exclusive ownership.
template<int L>
__device__ __forceinline__ void fwd_stage(float2* X, int t)
{
    const int q    = L >> 2;
    const int blk  = t / q;
    const int pos  = t % q;
    const int base = blk * L + pos;
    const int i0 = P2(base), i1 = P2(base + q), i2 = P2(base + 2*q), i3 = P2(base + 3*q);

    float2 w1, w2, w3;
    tw3((float)pos * (6.283185307179586f / (float)L), w1, w2, w3);

    const float2 a0 = X[i0], a1 = X[i1], a2 = X[i2], a3 = X[i3];
    const float2 t0 = cadd(a0, a2);
    const float2 t1 = csub(a0, a2);
    const float2 t2 = cadd(a1, a3);
    const float2 t3 = csub(a1, a3);
    X[i0] = cadd(t0, t2);
    X[i1] = cmul(submuli(t1, t3), w1);
    X[i2] = cmul(csub(t0, t2), w2);
    X[i3] = cmul(addmuli(t1, t3), w3);
}

// Inverse radix-4 stage (un-twiddle by conj, inverse butterfly).
template<int L>
__device__ __forceinline__ void inv_stage(float2* X, int t)
{
    const int q    = L >> 2;
    const int blk  = t / q;
    const int pos  = t % q;
    const int base = blk * L + pos;
    const int i0 = P2(base), i1 = P2(base + q), i2 = P2(base + 2*q), i3 = P2(base + 3*q);

    float2 w1, w2, w3;
    tw3((float)pos * (6.283185307179586f / (float)L), w1, w2, w3);

    const float2 a0 = X[i0];
    const float2 a1 = cmulc(X[i1], w1);
    const float2 a2 = cmulc(X[i2], w2);
    const float2 a3 = cmulc(X[i3], w3);
    const float2 t0 = cadd(a0, a2);
    const float2 t1 = csub(a0, a2);
    const float2 t2 = cadd(a1, a3);
    const float2 t3 = csub(a1, a3);
    X[i0] = cadd(t0, t2);
    X[i1] = addmuli(t1, t3);
    X[i2] = csub(t0, t2);
    X[i3] = submuli(t1, t3);
}

// Radix-2 stage L=2 (thread-local pairs; same butterfly fwd and inv).
__device__ __forceinline__ void r2_stage(float2* X, int t)
{
    const int b = 4 * t;
    const int i0 = P2(b), i1 = P2(b + 1), i2 = P2(b + 2), i3 = P2(b + 3);
    const float2 a0 = X[i0], a1 = X[i1], a2 = X[i2], a3 = X[i3];
    X[i0] = cadd(a0, a1);
    X[i1] = csub(a0, a1);
    X[i2] = cadd(a2, a3);
    X[i3] = csub(a2, a3);
}

// Middle unit for pair (k, 512-k): rfft combine + square + inverse-pack.
// Reads/writes only its own two positions. 1/512 folded into QS.
__device__ __forceinline__ void middle_unit(float2* X, int k)
{
    const int pk = P2(rev_inv(k));
    const int pm = P2(rev_inv((HF - k) & (HF - 1)));

    const float th = (float)k * 0.006135923151542565f;    // pi/512, th <= pi/2
    const float2 w = make_float2(fcos(th), -fsin(th));    // W1024^k

    const float2 Uk = X[pk];
    const float2 Um = X[pm];

    const float2 E = make_float2(0.5f * (Uk.x + Um.x), 0.5f * (Uk.y - Um.y));
    const float2 O = make_float2(0.5f * (Uk.y + Um.y), 0.5f * (Um.x - Uk.x));

    const float2 wO = cmul(O, w);
    const float2 Xp = cadd(E, wO);             // X[k]
    const float2 Xm = csub(E, wO);             // X[k+512]

    const float2 P = csq(Xp);
    const float2 M = csq(Xm);
    const float QS = 9.765625e-4f;             // 0.5 * (1/512)
    const float2 S  = make_float2(QS * (P.x + M.x), QS * (P.y + M.y));
    const float2 Dm = make_float2(QS * (P.x - M.x), QS * (P.y - M.y));

    const float2 r = cmulc(Dm, w);             // conj(w)*Dm
    const float2 Vk = make_float2(S.x - r.y, S.y + r.x);     // S + i*r

    const float2 q2 = cmul(make_float2(Dm.x, -Dm.y), w);     // w*conj(Dm)
    const float2 Vm = make_float2(S.x - q2.y, -S.y + q2.x);  // conj(S)+i*q2

    X[pk] = Vk;
    X[pm] = Vm;
}

__global__ __launch_bounds__(THREADS, 3)
void mcf_r16_kernel(const float* __restrict__ x1,
                    const float* __restrict__ x2,
                    const float* __restrict__ x3,
                    float* __restrict__ out)
{
    __shared__ __align__(16) float2 X[546];     // 512 + padding

    const int bx  = blockIdx.x;                 // 0..383: one row
    const int arr = bx >> 7;
    const int row = bx & 127;

    const float* xp = (arr == 0) ? x1 : ((arr == 1) ? x2 : x3);
    const float* xr = xp + (size_t)row * N_CONV;

    const int t = threadIdx.x;

    // Prologue: pack u[m] = x[2m] + i*x[2m+1]; thread t owns m = 4t..4t+3.
    {
        const float4 v0 = ((const float4*)xr)[2 * t];
        const float4 v1 = ((const float4*)xr)[2 * t + 1];
        const int b = 4 * t;
        X[P2(b)]     = make_float2(v0.x, v0.y);
        X[P2(b + 1)] = make_float2(v0.z, v0.w);
        X[P2(b + 2)] = make_float2(v1.x, v1.y);
        X[P2(b + 3)] = make_float2(v1.z, v1.w);
    }
    __syncthreads();

    // Forward FFT-512.
    fwd_stage<512>(X, t); __syncthreads();
    fwd_stage<128>(X, t); __syncwarp();
    fwd_stage< 32>(X, t); __syncwarp();
    fwd_stage<  8>(X, t); __syncwarp();
    r2_stage(X, t);
    __syncthreads();   // middle reads scattered global positions

    // Middle: rfft combine + square + inverse-pack, pairwise in-place.
    middle_unit(X, 2 * t);
    middle_unit(X, 2 * t + 1);
    if (t == 0) middle_unit(X, 256);
    __syncthreads();

    // Inverse: exact unwind.
    r2_stage(X, t);       __syncwarp();
    inv_stage<  8>(X, t); __syncwarp();
    inv_stage< 32>(X, t); __syncwarp();
    inv_stage<128>(X, t); __syncthreads();

    // Final inverse stage L=512 fused with epilogue de-pack to gmem.
    // (normalization already folded into the middle)
    {
        const int i0 = P2(t), i1 = P2(t + 128), i2 = P2(t + 256), i3 = P2(t + 384);
        float2 w1, w2, w3;
        tw3((float)t * (6.283185307179586f / 512.0f), w1, w2, w3);

        const float2 a0 = X[i0];
        const float2 a1 = cmulc(X[i1], w1);
        const float2 a2 = cmulc(X[i2], w2);
        const float2 a3 = cmulc(X[i3], w3);

        const float2 t0 = cadd(a0, a2);
        const float2 t1 = csub(a0, a2);
        const float2 t2 = cadd(a1, a3);
        const float2 t3 = csub(a1, a3);

        float2* orow = (float2*)(out + (size_t)arr * 128 * N_CONV
                                     + (size_t)row * N_CONV);
        // v[n] at n = t + 128m -> y[2n] = Re, y[2n+1] = Im.
        orow[t]       = cadd(t0, t2);
        orow[t + 128] = addmuli(t1, t3);
        orow[t + 256] = csub(t0, t2);
        orow[t + 384] = submuli(t1, t3);
    }
}

extern "C" void kernel_launch(void* const* d_in, const int* in_sizes, int n_in,
                              void* d_out, int out_size)
{
    const float* x1 = (const float*)d_in[0];
    const float* x2 = (const float*)d_in[1];
    const float* x3 = (const float*)d_in[2];
    float* out = (float*)d_out;

    mcf_r16_kernel<<<384, THREADS>>>(x1, x2, x3, out);
}